// round 17
// baseline (speedup 1.0000x reference)
#include <cuda_runtime.h>
#include <math.h>

// Problem constants
#define D_     512
#define TD_    1024
#define NSYM_  512
#define NCON_  64
#define NV_    256
#define NPOS_  16384
#define DEPTH_ 6
#define EPS_   1e-8f
#define CC_    0.25f
#define SCALE_ 0.04419417382415922f   // 512^-0.5

#define NBLOCKS 592    // 4 blocks/SM x 148 SMs
#define NTHR    128

typedef unsigned long long ull;
typedef unsigned int uint32;

// ---------------------------------------------------------------------------
// Tables
// ---------------------------------------------------------------------------
__device__ float g_W2[TD_*TD_];
__device__ float g_embed[NV_*TD_];
__device__ float g_z0[NV_*TD_];
__device__ float g_cellTab[NSYM_*TD_];
__device__ float g_C2[NSYM_*TD_];
__device__ float g_C3[NSYM_*TD_];
__device__ float g_lookOut[NSYM_*NV_];
__device__ float g_Ksym[NSYM_*D_];
__device__ float g_Vsym[NSYM_*TD_];
__device__ float g_Qtab[NSYM_*D_];
__device__ float g_QK[NSYM_*NSYM_];
__device__ float g_CS[NSYM_*NSYM_];
__device__ float g_VS[NSYM_*NSYM_];
__device__ float g_Z0S[NV_*NSYM_];
__device__ float g_sym2[NSYM_];
__device__ float g_conDist[NSYM_];
__device__ int   g_hist[NV_];
__device__ int   g_fin[NV_];
__device__ float g_symLv[NV_];
__device__ float g_conLv[NV_];
__device__ ull   g_barCnt;       // monotone grid barrier (replay-safe)
__device__ int   g_work;         // ticket counter (reset each launch)
__device__ int   g_cnt[17];      // per-table done counters (reset each launch)

// ---------------------------------------------------------------------------
// Grid-wide barrier (all NBLOCKS resident; monotone counter)
// ---------------------------------------------------------------------------
__device__ __forceinline__ void grid_barrier()
{
    __syncthreads();
    if (threadIdx.x == 0) {
        __threadfence();
        ull t = atomicAdd(&g_barCnt, 1ULL) + 1ULL;
        ull target = ((t - 1ULL) / NBLOCKS + 1ULL) * NBLOCKS;
        while (*(volatile ull*)&g_barCnt < target) { }
        __threadfence();
    }
    __syncthreads();
}

// ---------------------------------------------------------------------------
// tf32 helpers (R11, proven)
// ---------------------------------------------------------------------------
__device__ __forceinline__ void mma_tf32(float* d, const uint32* a, const uint32* b)
{
    asm volatile("mma.sync.aligned.m16n8k8.row.col.f32.tf32.tf32.f32 "
        "{%0,%1,%2,%3}, {%4,%5,%6,%7}, {%8,%9}, {%0,%1,%2,%3};"
        : "+f"(d[0]), "+f"(d[1]), "+f"(d[2]), "+f"(d[3])
        : "r"(a[0]), "r"(a[1]), "r"(a[2]), "r"(a[3]), "r"(b[0]), "r"(b[1]));
}

__device__ __forceinline__ void split_store22(uint32* H, uint32* L, int rowBase,
                                              int q, float4 v)
{
    int base = rowBase + (q >> 1) * 8 + (q & 1);
#pragma unroll
    for (int c = 0; c < 4; c++) {
        float f = ((float*)&v)[c];
        uint32 h; asm("cvt.rna.tf32.f32 %0, %1;" : "=r"(h) : "f"(f));
        float r = f - __uint_as_float(h);
        uint32 l; asm("cvt.rna.tf32.f32 %0, %1;" : "=r"(l) : "f"(r));
        H[base + c*2] = h; L[base + c*2] = l;
    }
}

// ---------------------------------------------------------------------------
// Tensor-core GEMM tile 64x64, 128 threads, 3xTF32 (R11, proven)
// ---------------------------------------------------------------------------
#define RS 22
#define TGSM (4*64*RS)   // 5632 words = 22528 B

template<int CELL>
__device__ void dev_gemm_tc(const float* __restrict__ A, const float* __restrict__ B,
                            const float* __restrict__ bias, float* __restrict__ C,
                            int N, int K, int bx, int by, float* sm)
{
    uint32* Ah = (uint32*)sm;
    uint32* Al = Ah + 64*RS;
    uint32* Bh = Al + 64*RS;
    uint32* Bl = Bh + 64*RS;

    const int tid  = threadIdx.x;
    const int warp = tid >> 5, lane = tid & 31;
    const int g = lane >> 2, tg = lane & 3;
    const int wm = (warp & 1) * 32, wn = (warp >> 1) * 32;
    const int m0 = by * 64, n0 = bx * 64;

    const int r0 = tid >> 2, q = tid & 3;
    const int r1 = r0 + 32;

    const float* gA0 = A + (size_t)(m0 + r0) * K + q * 4;
    const float* gA1 = A + (size_t)(m0 + r1) * K + q * 4;
    const float* gB0 = B + (size_t)(n0 + r0) * K + q * 4;
    const float* gB1 = B + (size_t)(n0 + r1) * K + q * 4;

    float d[2][4][4];
#pragma unroll
    for (int i = 0; i < 2; i++)
#pragma unroll
        for (int j = 0; j < 4; j++)
#pragma unroll
            for (int c = 0; c < 4; c++) d[i][j][c] = 0.f;

    const int nk = K >> 4;
    float4 pa0 = *(const float4*)(gA0);
    float4 pa1 = *(const float4*)(gA1);
    float4 pb0 = *(const float4*)(gB0);
    float4 pb1 = *(const float4*)(gB1);

    for (int t = 0; t < nk; t++) {
        split_store22(Ah, Al, r0*RS, q, pa0);
        split_store22(Ah, Al, r1*RS, q, pa1);
        split_store22(Bh, Bl, r0*RS, q, pb0);
        split_store22(Bh, Bl, r1*RS, q, pb1);
        __syncthreads();

        if (t + 1 < nk) {
            pa0 = *(const float4*)(gA0 + (t+1)*16);
            pa1 = *(const float4*)(gA1 + (t+1)*16);
            pb0 = *(const float4*)(gB0 + (t+1)*16);
            pb1 = *(const float4*)(gB1 + (t+1)*16);
        }

#pragma unroll
        for (int kf = 0; kf < 2; kf++) {
            const int pbase = kf*8 + tg*2;
            uint32 ah[2][4], al[2][4];
#pragma unroll
            for (int mf = 0; mf < 2; mf++) {
                int ra = (wm + mf*16 + g)*RS + pbase;
                int rb = ra + 8*RS;
                uint2 h0 = *(const uint2*)(Ah + ra);
                uint2 h1 = *(const uint2*)(Ah + rb);
                uint2 l0 = *(const uint2*)(Al + ra);
                uint2 l1 = *(const uint2*)(Al + rb);
                ah[mf][0] = h0.x; ah[mf][1] = h1.x; ah[mf][2] = h0.y; ah[mf][3] = h1.y;
                al[mf][0] = l0.x; al[mf][1] = l1.x; al[mf][2] = l0.y; al[mf][3] = l1.y;
            }
            uint32 bh[4][2], bl[4][2];
#pragma unroll
            for (int nf = 0; nf < 4; nf++) {
                int rb = (wn + nf*8 + g)*RS + pbase;
                uint2 h = *(const uint2*)(Bh + rb);
                uint2 l = *(const uint2*)(Bl + rb);
                bh[nf][0] = h.x; bh[nf][1] = h.y;
                bl[nf][0] = l.x; bl[nf][1] = l.y;
            }
#pragma unroll
            for (int mf = 0; mf < 2; mf++)
#pragma unroll
                for (int nf = 0; nf < 4; nf++) {
                    mma_tf32(d[mf][nf], ah[mf], bh[nf]);
                    mma_tf32(d[mf][nf], al[mf], bh[nf]);
                    mma_tf32(d[mf][nf], ah[mf], bl[nf]);
                }
        }
        __syncthreads();
    }

    if (!CELL) {
#pragma unroll
        for (int mf = 0; mf < 2; mf++)
#pragma unroll
            for (int nf = 0; nf < 4; nf++) {
                int r = m0 + wm + mf*16 + g;
                int c = n0 + wn + nf*8 + 2*tg;
                float b0v = bias ? bias[c]   : 0.f;
                float b1v = bias ? bias[c+1] : 0.f;
                C[(size_t)r*N + c]         = d[mf][nf][0] + b0v;
                C[(size_t)r*N + c + 1]     = d[mf][nf][1] + b1v;
                C[(size_t)(r+8)*N + c]     = d[mf][nf][2] + b0v;
                C[(size_t)(r+8)*N + c + 1] = d[mf][nf][3] + b1v;
            }
    } else {
#pragma unroll
        for (int mf = 0; mf < 2; mf++)
#pragma unroll
            for (int nf = 0; nf < 4; nf++) {
                int r = m0 + wm + mf*16 + g;
                int p = ((n0 + wn + nf*8) >> 1) + tg;
#pragma unroll
                for (int h = 0; h < 2; h++) {
                    int rr = r + h*8;
                    float lr = d[mf][nf][0 + 2*h], li = d[mf][nf][1 + 2*h];
                    float mm = sqrtf(lr*lr + li*li + EPS_);
                    C[(size_t)rr*TD_ + p]      = tanhf(lr / (1.f + mm));
                    C[(size_t)rr*TD_ + p + D_] = tanhf(li / (1.f + mm));
                }
            }
    }
}

// ---------------------------------------------------------------------------
// Trajectory (one unit = one vocab id, 128 threads) — R11, proven
// ---------------------------------------------------------------------------
__device__ void dev_trajectory(int v, float* sm)
{
    float* red   = sm;
    float* sdist = sm + 128;
    int*   sidx  = (int*)(sm + 256);
    int*   memIdx= (int*)(sm + 384);
    float* wsh   = sm + 392;
    float* shconf= sm + 400;
    const int tid = threadIdx.x;

    float part = 0.f;
    for (int i = tid; i < TD_; i += NTHR) { float z = g_z0[(size_t)v*TD_ + i]; part += z*z; }
    red[tid] = part; __syncthreads();
    for (int st = 64; st > 0; st >>= 1) { if (tid < st) red[tid] += red[tid+st]; __syncthreads(); }
    float z2 = red[0];
    __syncthreads();

    float bd = 1e30f; int bi = 0;
    for (int kp = tid; kp < NSYM_; kp += NTHR) {
        float d = z2 + g_sym2[kp] - 2.f*g_Z0S[(size_t)v*NSYM_ + kp];
        if (d < bd) { bd = d; bi = kp; }
    }
    sdist[tid] = bd; sidx[tid] = bi; __syncthreads();
    for (int st = 64; st > 0; st >>= 1) {
        if (tid < st) {
            float d2 = sdist[tid+st]; int i2 = sidx[tid+st];
            if (d2 < sdist[tid] || (d2 == sdist[tid] && i2 < sidx[tid])) { sdist[tid] = d2; sidx[tid] = i2; }
        }
        __syncthreads();
    }
    int si = sidx[0]; float sd = sdist[0];
    if (tid == 0) { memIdx[0] = si; shconf[0] = 1.f/(1.f + sd); }
    float symL = sd;
    float conL = g_conDist[si];
    __syncthreads();

    for (int d = 1; d < DEPTH_; d++) {
        int k = memIdx[d-1];
        if (tid == 0) {
            float sc[DEPTH_]; float mx = -1e30f;
            float cf = shconf[0];
            for (int j = 0; j < d; j++) {
                float s = g_QK[(size_t)k*NSYM_ + memIdx[j]] * SCALE_ * cf;
                sc[j] = s; if (s > mx) mx = s;
            }
            float se = 0.f;
            for (int j = 0; j < d; j++) { sc[j] = expf(sc[j]-mx); se += sc[j]; }
            for (int j = 0; j < d; j++) wsh[j] = sc[j]/se;
        }
        __syncthreads();

        part = 0.f;
        for (int i = tid; i < TD_; i += NTHR) {
            float z = g_cellTab[(size_t)k*TD_ + i];
            for (int j = 0; j < d; j++)
                z += 0.1f * wsh[j] * g_Vsym[(size_t)memIdx[j]*TD_ + i];
            part += z*z;
        }
        red[tid] = part; __syncthreads();
        for (int st = 64; st > 0; st >>= 1) { if (tid < st) red[tid] += red[tid+st]; __syncthreads(); }
        z2 = red[0];
        __syncthreads();

        bd = 1e30f; bi = 0;
        for (int kp = tid; kp < NSYM_; kp += NTHR) {
            float zdot = g_CS[(size_t)k*NSYM_ + kp];
            for (int j = 0; j < d; j++)
                zdot += 0.1f * wsh[j] * g_VS[(size_t)memIdx[j]*NSYM_ + kp];
            float dist = z2 + g_sym2[kp] - 2.f*zdot;
            if (dist < bd) { bd = dist; bi = kp; }
        }
        sdist[tid] = bd; sidx[tid] = bi; __syncthreads();
        for (int st = 64; st > 0; st >>= 1) {
            if (tid < st) {
                float d2 = sdist[tid+st]; int i2 = sidx[tid+st];
                if (d2 < sdist[tid] || (d2 == sdist[tid] && i2 < sidx[tid])) { sdist[tid] = d2; sidx[tid] = i2; }
            }
            __syncthreads();
        }
        si = sidx[0]; sd = sdist[0];
        if (tid == 0) { memIdx[d] = si; shconf[0] = 1.f/(1.f + sd); }
        symL += sd;
        conL += g_conDist[si];
        __syncthreads();
    }

    if (tid == 0) {
        g_fin[v]   = memIdx[DEPTH_-1];
        g_symLv[v] = symL;
        g_conLv[v] = conL;
    }
    __syncthreads();
}

// ---------------------------------------------------------------------------
// Work-unit table (topologically sorted; deps always at lower tickets)
// ---------------------------------------------------------------------------
// [0,256)      W2 build (4 rows each)            -> cnt 0  (256)
// [256,288)    embed (8 vocab each)              -> cnt 1  (32)
// [288,416)    sym2 (4 rows)                     -> cnt 2  (128)
// [416,544)    conDist (4 rows)                  -> cnt 3  (128)
// 544          hist                              -> cnt 4  (1)
// [545,609)    Ksym                              -> cnt 5  (64)
// [609,737)    Vsym                              -> cnt 6  (128)
// [737,865)    cellTab   dep: cnt0==256          -> cnt 7  (128)
// [865,929)    z0        dep: cnt0, cnt1         -> cnt 8  (64)
// [929,993)    VS        dep: cnt6               -> cnt 9  (64)
// [993,1121)   C2        dep: cnt7               -> cnt 10 (128)
// [1121,1185)  Qtab      dep: cnt7               -> cnt 11 (64)
// [1185,1249)  CS        dep: cnt7               -> cnt 12 (64)
// [1249,1281)  Z0S       dep: cnt8               -> cnt 13 (32)
// [1281,1345)  QK        dep: cnt11, cnt5        -> cnt 14 (64)
// [1345,1473)  C3        dep: cnt10              -> cnt 15 (128)
// [1473,1505)  lookOut   dep: cnt15              -> cnt 16 (32)
// [1505,1761)  traj      dep: many               -> (none; final barrier)
#define NUNITS 1761

__device__ __forceinline__ void waitc(int idx, int target)
{
    volatile int* p = &g_cnt[idx];
    while (*p < target) __nanosleep(64);
}

__device__ void wait_deps(int u)
{
    if (u < 737) return;
    else if (u < 865)  { waitc(0, 256); }
    else if (u < 929)  { waitc(0, 256); waitc(1, 32); }
    else if (u < 993)  { waitc(6, 128); }
    else if (u < 1249) { waitc(7, 128); }            // C2, Qtab, CS
    else if (u < 1281) { waitc(8, 64); }
    else if (u < 1345) { waitc(11, 64); waitc(5, 64); }
    else if (u < 1473) { waitc(10, 128); }
    else if (u < 1505) { waitc(15, 128); }
    else {
        waitc(13, 32); waitc(14, 64); waitc(12, 64); waitc(9, 64);
        waitc(8, 64);  waitc(7, 128); waitc(6, 128); waitc(2, 128); waitc(3, 128);
    }
}

__device__ __forceinline__ int cnt_of(int u)
{
    if (u < 256) return 0;
    if (u < 288) return 1;
    if (u < 416) return 2;
    if (u < 544) return 3;
    if (u == 544) return 4;
    if (u < 609) return 5;
    if (u < 737) return 6;
    if (u < 865) return 7;
    if (u < 929) return 8;
    if (u < 993) return 9;
    if (u < 1121) return 10;
    if (u < 1185) return 11;
    if (u < 1249) return 12;
    if (u < 1281) return 13;
    if (u < 1345) return 14;
    if (u < 1473) return 15;
    if (u < 1505) return 16;
    return -1;
}

__device__ void exec_unit(int u,
    const float* mag, const float* phase, const float* Wr, const float* Wi,
    const float* qw, const float* qb, const float* kw, const float* kb,
    const float* vw, const float* vb, const float* dec_w, const float* dec_b,
    const float* sym, const float* con, const int* x, float* sm)
{
    const int tid = threadIdx.x;

    if (u < 256) {                              // W2 build: 4 rows
#pragma unroll
        for (int rr = 0; rr < 4; rr++) {
            int r = u*4 + rr;
            int n = r >> 1;
            int odd = r & 1;
            for (int k = tid*4; k < TD_; k += NTHR*4) {
                float4 v;
                if (k < D_) {
                    v = *(const float4*)((odd ? Wi : Wr) + (size_t)n*D_ + k);
                } else {
                    int k2 = k - D_;
                    if (odd) v = *(const float4*)(Wr + (size_t)n*D_ + k2);
                    else {
                        v = *(const float4*)(Wi + (size_t)n*D_ + k2);
                        v.x = -v.x; v.y = -v.y; v.z = -v.z; v.w = -v.w;
                    }
                }
                *(float4*)(g_W2 + (size_t)r*TD_ + k) = v;
            }
        }
    } else if (u < 288) {                       // embed: 8 vocab
        int base = (u - 256) * 8;
#pragma unroll
        for (int vv = 0; vv < 8; vv++) {
            int v = base + vv;
            for (int i = tid; i < D_; i += NTHR) {
                float r = mag[v*D_ + i];
                float t = phase[v*D_ + i];
                g_embed[v*TD_ + i]      = r * cosf(t);
                g_embed[v*TD_ + D_ + i] = r * sinf(t);
            }
        }
    } else if (u < 416) {                       // sym2: 4 rows
        int local = u - 288;
        int w = tid >> 5, lane = tid & 31;
        int row = local*4 + w;
        float s = 0.f;
        const float* src = sym + (size_t)row*TD_;
        for (int i = lane; i < TD_; i += 32) { float v = src[i]; s += v*v; }
#pragma unroll
        for (int o = 16; o > 0; o >>= 1) s += __shfl_down_sync(0xffffffffu, s, o);
        if (lane == 0) g_sym2[row] = s;
    } else if (u < 544) {                       // conDist: 4 rows
        int local = u - 416;
        int w = tid >> 5, lane = tid & 31;
        int row = local*4 + w;
        float sv[32];
#pragma unroll
        for (int c = 0; c < 32; c++) sv[c] = sym[(size_t)row*TD_ + c*32 + lane];
        float best = 1e30f;
        for (int j = 0; j < NCON_; j++) {
            const float* cj = con + (size_t)j*TD_;
            float s = 0.f;
#pragma unroll
            for (int c = 0; c < 32; c++) { float d = sv[c] - cj[c*32 + lane]; s += d*d; }
#pragma unroll
            for (int o = 16; o > 0; o >>= 1) s += __shfl_xor_sync(0xffffffffu, s, o);
            best = fminf(best, s);
        }
        if (lane == 0) g_conDist[row] = best;
    } else if (u == 544) {                      // histogram
        int* hist = (int*)sm;
        hist[tid] = 0; hist[tid + 128] = 0; __syncthreads();
        for (int i = tid; i < NPOS_; i += NTHR) atomicAdd(&hist[x[i]], 1);
        __syncthreads();
        g_hist[tid] = hist[tid];
        g_hist[tid + 128] = hist[tid + 128];
        __syncthreads();
    } else if (u < 609) {                       // Ksym
        int t = u - 545;
        dev_gemm_tc<0>(sym, kw, kb, g_Ksym, D_, TD_, t & 7, t >> 3, sm);
    } else if (u < 737) {                       // Vsym
        int t = u - 609;
        dev_gemm_tc<0>(sym, vw, vb, g_Vsym, TD_, TD_, t & 15, t >> 4, sm);
    } else if (u < 865) {                       // cellTab
        int t = u - 737;
        dev_gemm_tc<1>(sym, g_W2, nullptr, g_cellTab, TD_, TD_, t & 15, t >> 4, sm);
    } else if (u < 929) {                       // z0
        int t = u - 865;
        dev_gemm_tc<1>(g_embed, g_W2, nullptr, g_z0, TD_, TD_, t & 15, t >> 4, sm);
    } else if (u < 993) {                       // VS
        int t = u - 929;
        dev_gemm_tc<0>(g_Vsym, sym, nullptr, g_VS, NSYM_, TD_, t & 7, t >> 3, sm);
    } else if (u < 1121) {                      // C2
        int t = u - 993;
        dev_gemm_tc<1>(g_cellTab, g_W2, nullptr, g_C2, TD_, TD_, t & 15, t >> 4, sm);
    } else if (u < 1185) {                      // Qtab
        int t = u - 1121;
        dev_gemm_tc<0>(g_cellTab, qw, qb, g_Qtab, D_, TD_, t & 7, t >> 3, sm);
    } else if (u < 1249) {                      // CS
        int t = u - 1185;
        dev_gemm_tc<0>(g_cellTab, sym, nullptr, g_CS, NSYM_, TD_, t & 7, t >> 3, sm);
    } else if (u < 1281) {                      // Z0S
        int t = u - 1249;
        dev_gemm_tc<0>(g_z0, sym, nullptr, g_Z0S, NSYM_, TD_, t & 7, t >> 3, sm);
    } else if (u < 1345) {                      // QK
        int t = u - 1281;
        dev_gemm_tc<0>(g_Qtab, g_Ksym, nullptr, g_QK, NSYM_, D_, t & 7, t >> 3, sm);
    } else if (u < 1473) {                      // C3
        int t = u - 1345;
        dev_gemm_tc<1>(g_C2, g_W2, nullptr, g_C3, TD_, TD_, t & 15, t >> 4, sm);
    } else if (u < 1505) {                      // lookOut
        int t = u - 1473;
        dev_gemm_tc<0>(g_C3, dec_w, dec_b, g_lookOut, NV_, TD_, t & 3, t >> 2, sm);
    } else {                                    // trajectory
        dev_trajectory(u - 1505, sm);
    }
}

// ---------------------------------------------------------------------------
// Persistent mega-kernel with dependency scheduler
// ---------------------------------------------------------------------------
__global__ __launch_bounds__(NTHR, 4)
void mega_kernel(const int* __restrict__ x,
                 const float* __restrict__ mag, const float* __restrict__ phase,
                 const float* __restrict__ Wr,  const float* __restrict__ Wi,
                 const float* __restrict__ qw,  const float* __restrict__ qb,
                 const float* __restrict__ kw,  const float* __restrict__ kb,
                 const float* __restrict__ vw,  const float* __restrict__ vb,
                 const float* __restrict__ dec_w, const float* __restrict__ dec_b,
                 const float* __restrict__ sym, const float* __restrict__ con,
                 float* __restrict__ out, int writeLoss)
{
    __shared__ float sm[TGSM];
    __shared__ int shU;
    const int tid = threadIdx.x;

    // reset scheduler state (block 0), then sync all blocks
    if (blockIdx.x == 0 && tid == 0) {
        g_work = 0;
#pragma unroll
        for (int i = 0; i < 17; i++) g_cnt[i] = 0;
    }
    grid_barrier();

    // scheduler loop
    while (true) {
        if (tid == 0) shU = atomicAdd(&g_work, 1);
        __syncthreads();
        int u = shU;
        __syncthreads();
        if (u >= NUNITS) break;

        if (tid == 0) wait_deps(u);
        __syncthreads();
        __threadfence();

        exec_unit(u, mag, phase, Wr, Wi, qw, qb, kw, kb, vw, vb,
                  dec_w, dec_b, sym, con, x, sm);
        __syncthreads();

        if (tid == 0) {
            int ci = cnt_of(u);
            if (ci >= 0) { __threadfence(); atomicAdd(&g_cnt[ci], 1); }
        }
    }

    grid_barrier();

    // scatter + losses
    for (int u = blockIdx.x; u < 8193; u += NBLOCKS) {
        if (u < 8192) {
            int gid = u * NTHR + tid;
            int p = gid >> 6;
            int c = gid & 63;
            int v = __ldg(&x[p]);
            int f = g_fin[v];
            ((float4*)out)[gid] = ((const float4*)(g_lookOut + (size_t)f*NV_))[c];
        } else {
            float* red = sm;
            float h0 = (float)g_hist[tid], h1 = (float)g_hist[tid + 128];
            float s = h0 * g_symLv[tid] + h1 * g_symLv[tid + 128];
            float c = h0 * g_conLv[tid] + h1 * g_conLv[tid + 128];

            red[tid] = s; __syncthreads();
            for (int st = 64; st > 0; st >>= 1) { if (tid < st) red[tid] += red[tid+st]; __syncthreads(); }
            float st_tot = red[0]; __syncthreads();

            red[tid] = c; __syncthreads();
            for (int st = 64; st > 0; st >>= 1) { if (tid < st) red[tid] += red[tid+st]; __syncthreads(); }
            float ct_tot = red[0];

            if (tid == 0 && writeLoss) {
                float norm = (1.f + CC_) / (float)((size_t)NPOS_ * TD_);
                out[(size_t)NPOS_*NV_]     = st_tot * norm;
                out[(size_t)NPOS_*NV_ + 1] = ct_tot * norm;
            }
            __syncthreads();
        }
    }
}

// ---------------------------------------------------------------------------
// Host launcher
// ---------------------------------------------------------------------------
extern "C" void kernel_launch(void* const* d_in, const int* in_sizes, int n_in,
                              void* d_out, int out_size)
{
    const int*   x     = (const int*)d_in[0];
    const float* mag   = (const float*)d_in[1];
    const float* phase = (const float*)d_in[2];
    const float* Wr    = (const float*)d_in[3];
    const float* Wi    = (const float*)d_in[4];
    const float* qw    = (const float*)d_in[5];
    const float* qb    = (const float*)d_in[6];
    const float* kw    = (const float*)d_in[7];
    const float* kb    = (const float*)d_in[8];
    const float* vw    = (const float*)d_in[9];
    const float* vb    = (const float*)d_in[10];
    const float* dec_w = (const float*)d_in[11];
    const float* dec_b = (const float*)d_in[12];
    const float* sym   = (const float*)d_in[13];
    const float* con   = (const float*)d_in[14];
    float* out = (float*)d_out;

    int writeLoss = (out_size >= NPOS_*NV_ + 2) ? 1 : 0;

    mega_kernel<<<NBLOCKS, NTHR>>>(x, mag, phase, Wr, Wi, qw, qb, kw, kb,
                                   vw, vb, dec_w, dec_b, sym, con, out, writeLoss);
}